// round 6
// baseline (speedup 1.0000x reference)
#include <cuda_runtime.h>
#include <math.h>

#define E_TOTAL 400000
#define NNODES  12500
#define T1      128     // edges per CTA, kernel 1
#define PH      68      // smem row pitch (floats)
#define FULLC   25
#define MALL    19
#define NSPEC   90

typedef unsigned long long ull;

// scratch (static device globals; no allocation in kernel_launch)
__device__ float F_buf[(size_t)E_TOTAL * 320];
__device__ int   d_cnt[NNODES];
__device__ int   d_cur[NNODES];
__device__ int   d_offs[NNODES + 1];
__device__ int   d_eids[E_TOTAL];
__device__ float SPb[NSPEC * 64];                // semb @ W1[128:192] + b1
__device__ float RPb[NSPEC * 64];                // remb @ W1[192:256]

__device__ __forceinline__ ull pack2(float x) {
    ull r; asm("mov.b64 %0,{%1,%1};" : "=l"(r) : "f"(x)); return r;
}
__device__ __forceinline__ ull pack2xy(float x, float y) {
    ull r; asm("mov.b64 %0,{%1,%2};" : "=l"(r) : "f"(x), "f"(y)); return r;
}
__device__ __forceinline__ void fma2(ull& d, ull a, ull b) {
    asm("fma.rn.f32x2 %0,%1,%2,%0;" : "+l"(d) : "l"(a), "l"(b));
}
__device__ __forceinline__ float2 unpk(ull v) {
    float2 o; asm("mov.b64 {%0,%1},%2;" : "=f"(o.x), "=f"(o.y) : "l"(v)); return o;
}

// permuted float4 slot within a 64-float W row (conflict-free b-loads)
__device__ __forceinline__ int wperm(int c4) { return ((c4 & 1) << 3) | (c4 >> 1); }

// ---------------------------------------------------------------- CSR build
__global__ void zero_kernel() {
    int i = blockIdx.x * blockDim.x + threadIdx.x;
    if (i < NNODES) { d_cnt[i] = 0; d_cur[i] = 0; }
}
__global__ void hist_kernel(const int* __restrict__ receivers) {
    int e = blockIdx.x * blockDim.x + threadIdx.x;
    if (e < E_TOTAL) atomicAdd(&d_cnt[receivers[e]], 1);
}
__global__ void scan_kernel() {
    __shared__ int s[1024];
    const int CH = (NNODES + 1023) / 1024;   // 13
    int t = threadIdx.x;
    int base = t * CH;
    int loc[CH];
    int sum = 0;
    #pragma unroll
    for (int i = 0; i < CH; ++i) {
        int v = (base + i < NNODES) ? d_cnt[base + i] : 0;
        loc[i] = sum; sum += v;
    }
    s[t] = sum;
    __syncthreads();
    for (int off = 1; off < 1024; off <<= 1) {
        int v = s[t];
        int u = (t >= off) ? s[t - off] : 0;
        __syncthreads();
        s[t] = v + u;
        __syncthreads();
    }
    int excl = (t > 0) ? s[t - 1] : 0;
    #pragma unroll
    for (int i = 0; i < CH; ++i)
        if (base + i < NNODES) d_offs[base + i] = excl + loc[i];
    if (t == 1023) d_offs[NNODES] = s[1023];
}
__global__ void fill_kernel(const int* __restrict__ receivers) {
    int e = blockIdx.x * blockDim.x + threadIdx.x;
    if (e < E_TOTAL) {
        int r = receivers[e];
        int pos = atomicAdd(&d_cur[r], 1);
        d_eids[d_offs[r] + pos] = e;
    }
}

// -------------------------------------------- species projection precompute
__global__ void species_kernel(const float* __restrict__ semb,
                               const float* __restrict__ remb,
                               const float* __restrict__ W1,
                               const float* __restrict__ b1)
{
    int s = blockIdx.x;        // 0..89
    int c = threadIdx.x;       // 0..63
    float sp = b1[c], rp = 0.0f;
    #pragma unroll 8
    for (int k = 0; k < 64; ++k) {
        sp += semb[s * 64 + k] * W1[(128 + k) * 64 + c];
        rp += remb[s * 64 + k] * W1[(192 + k) * 64 + c];
    }
    SPb[s * 64 + c] = sp;
    RPb[s * 64 + c] = rp;
}

// ---------------------------------------------------------------- MLP GEMM
// 8 rows x 8 cols per thread (128 threads cover 128 rows x 64 cols).
// W in smem is PERMUTED (wperm); b-loads conflict-free, a-loads broadcast.
__device__ __forceinline__ void gemm64(const float* __restrict__ As,
                                       const ull*  __restrict__ Wp,
                                       int row0, int cj, ull acc[32])
{
    #pragma unroll 2
    for (int k4 = 0; k4 < 16; ++k4) {
        float a8[8][4];
        #pragma unroll
        for (int r = 0; r < 8; ++r) {
            float4 v = *(const float4*)(As + (row0 + r) * PH + 4 * k4);
            a8[r][0] = v.x; a8[r][1] = v.y; a8[r][2] = v.z; a8[r][3] = v.w;
        }
        #pragma unroll
        for (int kk = 0; kk < 4; ++kk) {
            int k = 4 * k4 + kk;
            ulonglong2 bA = *(const ulonglong2*)(Wp + k * 32 + cj * 2);
            ulonglong2 bB = *(const ulonglong2*)(Wp + k * 32 + 16 + cj * 2);
            #pragma unroll
            for (int r = 0; r < 8; ++r) {
                ull p = pack2(a8[r][kk]);
                fma2(acc[r * 4 + 0], p, bA.x);
                fma2(acc[r * 4 + 1], p, bA.y);
                fma2(acc[r * 4 + 2], p, bB.x);
                fma2(acc[r * 4 + 3], p, bB.y);
            }
        }
    }
}

__device__ __forceinline__ void store_acc_smem(float* __restrict__ H, int row0, int cj,
                                               const ull acc[32], float4 bl, float4 bh)
{
    #pragma unroll
    for (int r = 0; r < 8; ++r) {
        float2 e0 = unpk(acc[4*r+0]); float2 e1 = unpk(acc[4*r+1]);
        float2 e2 = unpk(acc[4*r+2]); float2 e3 = unpk(acc[4*r+3]);
        float* p = H + (row0 + r) * PH + cj * 8;
        *(float4*)(p)     = make_float4(e0.x + bl.x, e0.y + bl.y, e1.x + bl.z, e1.y + bl.w);
        *(float4*)(p + 4) = make_float4(e2.x + bh.x, e2.y + bh.y, e3.x + bh.z, e3.y + bh.w);
    }
}

// 4 warps, each normalizes 32 rows; lane owns 2 adjacent columns
__device__ __forceinline__ void ln_silu(float* __restrict__ Bs,
                                        const float* __restrict__ g,
                                        const float* __restrict__ be,
                                        int lane, int warp)
{
    float2 gv = *(const float2*)(g  + 2 * lane);
    float2 bv = *(const float2*)(be + 2 * lane);
    #pragma unroll
    for (int rr = 0; rr < 32; ++rr) {
        int row = warp * 32 + rr;
        float2 v = *(float2*)(Bs + row * PH + 2 * lane);
        float s  = v.x + v.y;
        float s2 = v.x * v.x + v.y * v.y;
        #pragma unroll
        for (int o = 16; o > 0; o >>= 1) {
            s  += __shfl_xor_sync(0xffffffffu, s,  o);
            s2 += __shfl_xor_sync(0xffffffffu, s2, o);
        }
        float mu  = s * (1.0f / 64.0f);
        float var = s2 * (1.0f / 64.0f) - mu * mu;
        float rs  = rsqrtf(fmaxf(var, 0.0f) + 1e-5f);
        float x0 = (v.x - mu) * rs * gv.x + bv.x;
        float x1 = (v.y - mu) * rs * gv.y + bv.y;
        x0 = x0 / (1.0f + __expf(-x0));
        x1 = x1 / (1.0f + __expf(-x1));
        *(float2*)(Bs + row * PH + 2 * lane) = make_float2(x0, x1);
    }
}

#define SM1_FLOATS (T1 * PH + T1 * PH + 64 * 64 + 64)
#define SM1_BYTES  (SM1_FLOATS * 4 + 1024)

__global__ __launch_bounds__(128, 2)
void mlp_kernel(const int*   __restrict__ species,
                const float* __restrict__ dist,
                const int*   __restrict__ senders,
                const int*   __restrict__ receivers,
                const float* __restrict__ W1,
                const float* __restrict__ g1, const float* __restrict__ be1,
                const float* __restrict__ W2, const float* __restrict__ b2,
                const float* __restrict__ g2, const float* __restrict__ be2,
                const float* __restrict__ W3, const float* __restrict__ b3)
{
    extern __shared__ float sm[];
    float* Xc = sm;                     // aliased as H2 later
    float* H1 = Xc + T1 * PH;
    float* Ws = H1 + T1 * PH;
    int*   spS = (int*)(Ws + 64 * 64 + 64);
    int*   spR = spS + T1;

    const int tid  = threadIdx.x;       // 0..127
    const int lane = tid & 31;
    const int warp = tid >> 5;          // 0..3
    const int ri   = tid >> 3;          // 0..15 -> 8 rows each
    const int cj   = tid & 7;           // 0..7  -> 8 cols each
    const int row0 = 8 * ri;
    const int base = blockIdx.x * T1;

    spS[tid] = species[senders[base + tid]];
    spR[tid] = species[receivers[base + tid]];
    __syncthreads();

    // ---- stage 1 acc init from precomputed species projections (incl. b1)
    ull acc[32];
    #pragma unroll
    for (int r = 0; r < 8; ++r) {
        int row = row0 + r;
        int ss = spS[row], sr = spR[row];
        float4 u0 = ((const float4*)SPb)[ss * 16 + cj * 2];
        float4 u1 = ((const float4*)SPb)[ss * 16 + cj * 2 + 1];
        float4 v0 = ((const float4*)RPb)[sr * 16 + cj * 2];
        float4 v1 = ((const float4*)RPb)[sr * 16 + cj * 2 + 1];
        acc[4*r+0] = pack2xy(u0.x + v0.x, u0.y + v0.y);
        acc[4*r+1] = pack2xy(u0.z + v0.z, u0.w + v0.w);
        acc[4*r+2] = pack2xy(u1.x + v1.x, u1.y + v1.y);
        acc[4*r+3] = pack2xy(u1.z + v1.z, u1.w + v1.w);
    }

    // ---- stage 1: += dist @ W1[0:128] (2 chunks of 64)
    for (int kc = 0; kc < 2; ++kc) {
        __syncthreads();
        #pragma unroll
        for (int q = 0; q < 8; ++q) {
            int lin = tid + 128 * q;          // 1024 float4
            int k = lin >> 4, c4 = lin & 15;
            ((float4*)Ws)[k * 16 + wperm(c4)] = ((const float4*)W1)[(kc * 64 + k) * 16 + c4];
        }
        #pragma unroll
        for (int q = 0; q < 16; ++q) {
            int lin = tid + 128 * q;          // 2048 float4 = 128 rows x 16
            int row = lin >> 4, c4 = lin & 15;
            float4 v = ((const float4*)dist)[(size_t)(base + row) * 32 + kc * 16 + c4];
            *(float4*)(Xc + row * PH + c4 * 4) = v;
        }
        __syncthreads();
        gemm64(Xc, (const ull*)Ws, row0, cj, acc);
    }
    {
        float4 z = make_float4(0, 0, 0, 0);
        __syncthreads();
        store_acc_smem(H1, row0, cj, acc, z, z);
    }
    __syncthreads();
    ln_silu(H1, g1, be1, lane, warp);
    __syncthreads();

    // ---- stage 2: H2 = H1 @ W2 (H2 aliases Xc)
    #pragma unroll
    for (int q = 0; q < 8; ++q) {
        int lin = tid + 128 * q;
        int k = lin >> 4, c4 = lin & 15;
        ((float4*)Ws)[k * 16 + wperm(c4)] = ((const float4*)W2)[lin];
    }
    __syncthreads();
    #pragma unroll
    for (int i = 0; i < 32; ++i) acc[i] = 0ull;
    gemm64(H1, (const ull*)Ws, row0, cj, acc);
    {
        float4 bl = ((const float4*)b2)[cj * 2];
        float4 bh = ((const float4*)b2)[cj * 2 + 1];
        __syncthreads();
        store_acc_smem(Xc, row0, cj, acc, bl, bh);
    }
    __syncthreads();
    ln_silu(Xc, g2, be2, lane, warp);

    // ---- stage 3: F_m = H2 @ W3[:, 64m:64m+64] + b3 -> F_buf
    for (int m = 0; m < 5; ++m) {
        __syncthreads();
        #pragma unroll
        for (int q = 0; q < 8; ++q) {
            int lin = tid + 128 * q;
            int k = lin >> 4, c4 = lin & 15;
            ((float4*)Ws)[k * 16 + wperm(c4)] = ((const float4*)W3)[k * 80 + m * 16 + c4];
        }
        __syncthreads();
        #pragma unroll
        for (int i = 0; i < 32; ++i) acc[i] = 0ull;
        gemm64(Xc, (const ull*)Ws, row0, cj, acc);

        float4 bl = ((const float4*)b3)[m * 16 + cj * 2];
        float4 bh = ((const float4*)b3)[m * 16 + cj * 2 + 1];
        #pragma unroll
        for (int r = 0; r < 8; ++r) {
            float2 e0 = unpk(acc[4*r+0]); float2 e1 = unpk(acc[4*r+1]);
            float2 e2 = unpk(acc[4*r+2]); float2 e3 = unpk(acc[4*r+3]);
            float* p = F_buf + (size_t)(base + row0 + r) * 320 + m * 64 + cj * 8;
            *(float4*)(p)     = make_float4(e0.x + bl.x, e0.y + bl.y, e1.x + bl.z, e1.y + bl.w);
            *(float4*)(p + 4) = make_float4(e2.x + bh.x, e2.y + bh.y, e3.x + bh.z, e3.y + bh.w);
        }
    }
}

// --------------------------------- kernel 2: gather per node, no atomics
__global__ __launch_bounds__(256)
void wigner_gather(const float* __restrict__ wig,
                   const float* __restrict__ env,
                   float* __restrict__ out)
{
    __shared__ ull wbp[8][25 * 8];
    const int tid  = threadIdx.x;
    const int lane = tid & 31;
    const int warp = tid >> 5;
    const int node = blockIdx.x * 8 + warp;
    if (node >= NNODES) return;

    ull acc[FULLC];
    #pragma unroll
    for (int f = 0; f < FULLC; ++f) acc[f] = 0ull;

    const int beg = d_offs[node];
    const int end = d_offs[node + 1];
    ull* wp = wbp[warp];

    for (int idx = beg; idx < end; ++idx) {
        int e = d_eids[idx];
        float sc = env[e] * 0.2f;
        const float* wr = wig + (size_t)e * (FULLC * MALL);
        #pragma unroll
        for (int t = 0; t < 4; ++t) {
            int lin = lane + 32 * t;
            if (lin < 125) {
                int f = lin / 5;
                int m = lin - 5 * f;
                wp[f * 8 + m] = pack2(wr[f * MALL + m] * sc);
            }
        }
        __syncwarp();

        const ull* fp = (const ull*)(F_buf + (size_t)e * 320 + 2 * lane);
        ull fm0 = fp[0], fm1 = fp[32], fm2 = fp[64], fm3 = fp[96], fm4 = fp[128];

        #pragma unroll
        for (int f = 0; f < FULLC; ++f) {
            ulonglong2 wA = *(const ulonglong2*)(wp + f * 8);
            ulonglong2 wB = *(const ulonglong2*)(wp + f * 8 + 2);
            ull w4 = wp[f * 8 + 4];
            ull r = acc[f];
            fma2(r, wA.x, fm0);
            fma2(r, wA.y, fm1);
            fma2(r, wB.x, fm2);
            fma2(r, wB.y, fm3);
            fma2(r, w4,   fm4);
            acc[f] = r;
        }
        __syncwarp();
    }

    float* ob = out + (size_t)node * 1600 + 2 * lane;
    #pragma unroll
    for (int f = 0; f < FULLC; ++f) {
        float2 rv = unpk(acc[f]);
        *(float2*)(ob + f * 64) = rv;
    }
}

extern "C" void kernel_launch(void* const* d_in, const int* in_sizes, int n_in,
                              void* d_out, int out_size)
{
    const int*   species   = (const int*)  d_in[0];
    const float* dist      = (const float*)d_in[1];
    const int*   senders   = (const int*)  d_in[2];
    const int*   receivers = (const int*)  d_in[3];
    const float* wig       = (const float*)d_in[4];
    const float* env       = (const float*)d_in[5];
    const float* semb      = (const float*)d_in[6];
    const float* remb      = (const float*)d_in[7];
    const float* W1  = (const float*)d_in[8];
    const float* b1  = (const float*)d_in[9];
    const float* g1  = (const float*)d_in[10];
    const float* be1 = (const float*)d_in[11];
    const float* W2  = (const float*)d_in[12];
    const float* b2  = (const float*)d_in[13];
    const float* g2  = (const float*)d_in[14];
    const float* be2 = (const float*)d_in[15];
    const float* W3  = (const float*)d_in[16];
    const float* b3  = (const float*)d_in[17];
    float* out = (float*)d_out;

    cudaFuncSetAttribute(mlp_kernel,
                         cudaFuncAttributeMaxDynamicSharedMemorySize, SM1_BYTES);

    species_kernel<<<NSPEC, 64>>>(semb, remb, W1, b1);
    zero_kernel<<<(NNODES + 1023) / 1024, 1024>>>();
    hist_kernel<<<(E_TOTAL + 255) / 256, 256>>>(receivers);
    scan_kernel<<<1, 1024>>>();
    fill_kernel<<<(E_TOTAL + 255) / 256, 256>>>(receivers);
    mlp_kernel<<<E_TOTAL / T1, 128, SM1_BYTES>>>(
        species, dist, senders, receivers,
        W1, g1, be1, W2, b2, g2, be2, W3, b3);
    wigner_gather<<<(NNODES + 7) / 8, 256>>>(wig, env, out);
}

// round 7
// speedup vs baseline: 1.0782x; 1.0782x over previous
#include <cuda_runtime.h>
#include <math.h>

#define E_TOTAL 400000
#define NNODES  12500
#define T1      256     // edges per CTA, kernel 1
#define PH      66      // smem row pitch (floats): 8*66 % 32 == 16 -> conflict-free a-loads
#define FULLC   25
#define MALL    19
#define NSPEC   90

typedef unsigned long long ull;

// scratch (static device globals; no allocation in kernel_launch)
__device__ float F_buf[(size_t)E_TOTAL * 320];
__device__ int   d_cnt[NNODES];
__device__ int   d_cur[NNODES];
__device__ int   d_offs[NNODES + 1];
__device__ int   d_eids[E_TOTAL];
__device__ float SPb[NSPEC * 64];                // semb @ W1[128:192] + b1
__device__ float RPb[NSPEC * 64];                // remb @ W1[192:256]

__device__ __forceinline__ ull pack2(float x) {
    ull r; asm("mov.b64 %0,{%1,%1};" : "=l"(r) : "f"(x)); return r;
}
__device__ __forceinline__ ull pack2xy(float x, float y) {
    ull r; asm("mov.b64 %0,{%1,%2};" : "=l"(r) : "f"(x), "f"(y)); return r;
}
__device__ __forceinline__ void fma2(ull& d, ull a, ull b) {
    asm("fma.rn.f32x2 %0,%1,%2,%0;" : "+l"(d) : "l"(a), "l"(b));
}
__device__ __forceinline__ float2 unpk(ull v) {
    float2 o; asm("mov.b64 {%0,%1},%2;" : "=f"(o.x), "=f"(o.y) : "l"(v)); return o;
}

// permuted float4 slot within a 64-float W row (conflict-free b-loads)
__device__ __forceinline__ int wperm(int c4) { return ((c4 & 1) << 3) | (c4 >> 1); }

// ---------------------------------------------------------------- CSR build
__global__ void zero_kernel() {
    int i = blockIdx.x * blockDim.x + threadIdx.x;
    if (i < NNODES) { d_cnt[i] = 0; d_cur[i] = 0; }
}
__global__ void hist_kernel(const int* __restrict__ receivers) {
    int e = blockIdx.x * blockDim.x + threadIdx.x;
    if (e < E_TOTAL) atomicAdd(&d_cnt[receivers[e]], 1);
}
__global__ void scan_kernel() {
    __shared__ int s[1024];
    const int CH = (NNODES + 1023) / 1024;   // 13
    int t = threadIdx.x;
    int base = t * CH;
    int loc[CH];
    int sum = 0;
    #pragma unroll
    for (int i = 0; i < CH; ++i) {
        int v = (base + i < NNODES) ? d_cnt[base + i] : 0;
        loc[i] = sum; sum += v;
    }
    s[t] = sum;
    __syncthreads();
    for (int off = 1; off < 1024; off <<= 1) {
        int v = s[t];
        int u = (t >= off) ? s[t - off] : 0;
        __syncthreads();
        s[t] = v + u;
        __syncthreads();
    }
    int excl = (t > 0) ? s[t - 1] : 0;
    #pragma unroll
    for (int i = 0; i < CH; ++i)
        if (base + i < NNODES) d_offs[base + i] = excl + loc[i];
    if (t == 1023) d_offs[NNODES] = s[1023];
}
__global__ void fill_kernel(const int* __restrict__ receivers) {
    int e = blockIdx.x * blockDim.x + threadIdx.x;
    if (e < E_TOTAL) {
        int r = receivers[e];
        int pos = atomicAdd(&d_cur[r], 1);
        d_eids[d_offs[r] + pos] = e;
    }
}

// -------------------------------------------- species projection precompute
__global__ void species_kernel(const float* __restrict__ semb,
                               const float* __restrict__ remb,
                               const float* __restrict__ W1,
                               const float* __restrict__ b1)
{
    int s = blockIdx.x;        // 0..89
    int c = threadIdx.x;       // 0..63
    float sp = b1[c], rp = 0.0f;
    #pragma unroll 8
    for (int k = 0; k < 64; ++k) {
        sp += semb[s * 64 + k] * W1[(128 + k) * 64 + c];
        rp += remb[s * 64 + k] * W1[(192 + k) * 64 + c];
    }
    SPb[s * 64 + c] = sp;
    RPb[s * 64 + c] = rp;
}

// ---------------------------------------------------------------- MLP GEMM
// 8 rows x 8 cols per thread; 256 threads cover 256 rows x 64 cols.
// a staged per-k2 as float2 (register cap); W PERMUTED (wperm) in smem.
__device__ __forceinline__ void gemm64(const float* __restrict__ As,
                                       const ull*  __restrict__ Wp,
                                       int row0, int cj, ull acc[32])
{
    #pragma unroll 4
    for (int k2 = 0; k2 < 32; ++k2) {
        float2 a8[8];
        #pragma unroll
        for (int r = 0; r < 8; ++r)
            a8[r] = *(const float2*)(As + (row0 + r) * PH + 2 * k2);
        #pragma unroll
        for (int kk = 0; kk < 2; ++kk) {
            int k = 2 * k2 + kk;
            ulonglong2 bA = *(const ulonglong2*)(Wp + k * 32 + cj * 2);
            ulonglong2 bB = *(const ulonglong2*)(Wp + k * 32 + 16 + cj * 2);
            #pragma unroll
            for (int r = 0; r < 8; ++r) {
                ull p = pack2(kk ? a8[r].y : a8[r].x);
                fma2(acc[r * 4 + 0], p, bA.x);
                fma2(acc[r * 4 + 1], p, bA.y);
                fma2(acc[r * 4 + 2], p, bB.x);
                fma2(acc[r * 4 + 3], p, bB.y);
            }
        }
    }
}

__device__ __forceinline__ void store_acc_smem(float* __restrict__ H, int row0, int cj,
                                               const ull acc[32], float4 bl, float4 bh)
{
    #pragma unroll
    for (int r = 0; r < 8; ++r) {
        float2 e0 = unpk(acc[4*r+0]); float2 e1 = unpk(acc[4*r+1]);
        float2 e2 = unpk(acc[4*r+2]); float2 e3 = unpk(acc[4*r+3]);
        float* p = H + (row0 + r) * PH + cj * 8;
        *(float2*)(p)     = make_float2(e0.x + bl.x, e0.y + bl.y);
        *(float2*)(p + 2) = make_float2(e1.x + bl.z, e1.y + bl.w);
        *(float2*)(p + 4) = make_float2(e2.x + bh.x, e2.y + bh.y);
        *(float2*)(p + 6) = make_float2(e3.x + bh.z, e3.y + bh.w);
    }
}

// 8 warps, each normalizes 32 rows; lane owns 2 adjacent columns
__device__ __forceinline__ void ln_silu(float* __restrict__ Bs,
                                        const float* __restrict__ g,
                                        const float* __restrict__ be,
                                        int lane, int warp)
{
    float2 gv = *(const float2*)(g  + 2 * lane);
    float2 bv = *(const float2*)(be + 2 * lane);
    #pragma unroll
    for (int rr = 0; rr < 32; ++rr) {
        int row = warp * 32 + rr;
        float2 v = *(float2*)(Bs + row * PH + 2 * lane);
        float s  = v.x + v.y;
        float s2 = v.x * v.x + v.y * v.y;
        #pragma unroll
        for (int o = 16; o > 0; o >>= 1) {
            s  += __shfl_xor_sync(0xffffffffu, s,  o);
            s2 += __shfl_xor_sync(0xffffffffu, s2, o);
        }
        float mu  = s * (1.0f / 64.0f);
        float var = s2 * (1.0f / 64.0f) - mu * mu;
        float rs  = rsqrtf(fmaxf(var, 0.0f) + 1e-5f);
        float x0 = (v.x - mu) * rs * gv.x + bv.x;
        float x1 = (v.y - mu) * rs * gv.y + bv.y;
        x0 = x0 / (1.0f + __expf(-x0));
        x1 = x1 / (1.0f + __expf(-x1));
        *(float2*)(Bs + row * PH + 2 * lane) = make_float2(x0, x1);
    }
}

// smem: one tile buffer (X chunks -> H1 -> H2) + Ws + species idx
#define SM1_FLOATS (T1 * PH + 64 * 64 + 64)
#define SM1_BYTES  (SM1_FLOATS * 4 + 2048 + 1024)

__global__ __launch_bounds__(256, 2)
void mlp_kernel(const int*   __restrict__ species,
                const float* __restrict__ dist,
                const int*   __restrict__ senders,
                const int*   __restrict__ receivers,
                const float* __restrict__ W1,
                const float* __restrict__ g1, const float* __restrict__ be1,
                const float* __restrict__ W2, const float* __restrict__ b2,
                const float* __restrict__ g2, const float* __restrict__ be2,
                const float* __restrict__ W3, const float* __restrict__ b3)
{
    extern __shared__ float sm[];
    float* Xc = sm;                        // X chunk, then H1, then H2
    float* Ws = Xc + T1 * PH;
    int*   spS = (int*)(Ws + 64 * 64 + 64);
    int*   spR = spS + T1;

    const int tid  = threadIdx.x;          // 0..255
    const int lane = tid & 31;
    const int warp = tid >> 5;             // 0..7
    const int ri   = tid >> 3;             // 0..31 -> 8 rows each
    const int cj   = tid & 7;              // 0..7  -> 8 cols each
    const int row0 = 8 * ri;
    const int base = blockIdx.x * T1;

    {
        int eg = base + tid;
        if (eg >= E_TOTAL) eg = E_TOTAL - 1;
        spS[tid] = species[senders[eg]];
        spR[tid] = species[receivers[eg]];
    }
    __syncthreads();

    // ---- stage 1 acc init from precomputed species projections (incl. b1)
    ull acc[32];
    #pragma unroll
    for (int r = 0; r < 8; ++r) {
        int row = row0 + r;
        int ss = spS[row], sr = spR[row];
        float4 u0 = ((const float4*)SPb)[ss * 16 + cj * 2];
        float4 u1 = ((const float4*)SPb)[ss * 16 + cj * 2 + 1];
        float4 v0 = ((const float4*)RPb)[sr * 16 + cj * 2];
        float4 v1 = ((const float4*)RPb)[sr * 16 + cj * 2 + 1];
        acc[4*r+0] = pack2xy(u0.x + v0.x, u0.y + v0.y);
        acc[4*r+1] = pack2xy(u0.z + v0.z, u0.w + v0.w);
        acc[4*r+2] = pack2xy(u1.x + v1.x, u1.y + v1.y);
        acc[4*r+3] = pack2xy(u1.z + v1.z, u1.w + v1.w);
    }

    // ---- stage 1: += dist @ W1[0:128] (2 chunks of 64)
    for (int kc = 0; kc < 2; ++kc) {
        __syncthreads();
        #pragma unroll
        for (int q = 0; q < 4; ++q) {
            int lin = tid + 256 * q;          // 1024 float4
            int k = lin >> 4, c4 = lin & 15;
            ((float4*)Ws)[k * 16 + wperm(c4)] = ((const float4*)W1)[(kc * 64 + k) * 16 + c4];
        }
        #pragma unroll
        for (int q = 0; q < 32; ++q) {
            int lin = tid + 256 * q;          // 8192 float2 = 256 rows x 32
            int row = lin >> 5, c2 = lin & 31;
            int eg = base + row;
            if (eg >= E_TOTAL) eg = E_TOTAL - 1;
            float2 v = ((const float2*)dist)[(size_t)eg * 64 + kc * 32 + c2];
            *(float2*)(Xc + row * PH + c2 * 2) = v;
        }
        __syncthreads();
        gemm64(Xc, (const ull*)Ws, row0, cj, acc);
    }
    {
        float4 z = make_float4(0, 0, 0, 0);
        __syncthreads();
        store_acc_smem(Xc, row0, cj, acc, z, z);   // H1 overwrites X chunk
    }
    // load W2 while H1 settles (different smem region)
    #pragma unroll
    for (int q = 0; q < 4; ++q) {
        int lin = tid + 256 * q;
        int k = lin >> 4, c4 = lin & 15;
        ((float4*)Ws)[k * 16 + wperm(c4)] = ((const float4*)W2)[lin];
    }
    __syncthreads();
    ln_silu(Xc, g1, be1, lane, warp);
    __syncthreads();

    // ---- stage 2: H2 = H1 @ W2
    #pragma unroll
    for (int i = 0; i < 32; ++i) acc[i] = 0ull;
    gemm64(Xc, (const ull*)Ws, row0, cj, acc);
    {
        float4 bl = ((const float4*)b2)[cj * 2];
        float4 bh = ((const float4*)b2)[cj * 2 + 1];
        __syncthreads();
        store_acc_smem(Xc, row0, cj, acc, bl, bh); // H2 overwrites H1
    }
    __syncthreads();
    ln_silu(Xc, g2, be2, lane, warp);

    // ---- stage 3: F_m = H2 @ W3[:, 64m:64m+64] + b3 -> F_buf
    for (int m = 0; m < 5; ++m) {
        __syncthreads();
        #pragma unroll
        for (int q = 0; q < 4; ++q) {
            int lin = tid + 256 * q;
            int k = lin >> 4, c4 = lin & 15;
            ((float4*)Ws)[k * 16 + wperm(c4)] = ((const float4*)W3)[k * 80 + m * 16 + c4];
        }
        __syncthreads();
        #pragma unroll
        for (int i = 0; i < 32; ++i) acc[i] = 0ull;
        gemm64(Xc, (const ull*)Ws, row0, cj, acc);

        float4 bl = ((const float4*)b3)[m * 16 + cj * 2];
        float4 bh = ((const float4*)b3)[m * 16 + cj * 2 + 1];
        #pragma unroll
        for (int r = 0; r < 8; ++r) {
            int eg = base + row0 + r;
            if (eg >= E_TOTAL) continue;
            float2 e0 = unpk(acc[4*r+0]); float2 e1 = unpk(acc[4*r+1]);
            float2 e2 = unpk(acc[4*r+2]); float2 e3 = unpk(acc[4*r+3]);
            float* p = F_buf + (size_t)eg * 320 + m * 64 + cj * 8;
            *(float4*)(p)     = make_float4(e0.x + bl.x, e0.y + bl.y, e1.x + bl.z, e1.y + bl.w);
            *(float4*)(p + 4) = make_float4(e2.x + bh.x, e2.y + bh.y, e3.x + bh.z, e3.y + bh.w);
        }
    }
}

// --------------------------------- kernel 2: gather per node, no atomics
__global__ __launch_bounds__(256)
void wigner_gather(const float* __restrict__ wig,
                   const float* __restrict__ env,
                   float* __restrict__ out)
{
    __shared__ ull wbp[8][25 * 8];
    const int tid  = threadIdx.x;
    const int lane = tid & 31;
    const int warp = tid >> 5;
    const int node = blockIdx.x * 8 + warp;
    if (node >= NNODES) return;

    ull acc[FULLC];
    #pragma unroll
    for (int f = 0; f < FULLC; ++f) acc[f] = 0ull;

    const int beg = d_offs[node];
    const int end = d_offs[node + 1];
    ull* wp = wbp[warp];

    for (int idx = beg; idx < end; ++idx) {
        int e = d_eids[idx];
        float sc = env[e] * 0.2f;
        const float* wr = wig + (size_t)e * (FULLC * MALL);
        #pragma unroll
        for (int t = 0; t < 4; ++t) {
            int lin = lane + 32 * t;
            if (lin < 125) {
                int f = lin / 5;
                int m = lin - 5 * f;
                wp[f * 8 + m] = pack2(wr[f * MALL + m] * sc);
            }
        }
        __syncwarp();

        const ull* fp = (const ull*)(F_buf + (size_t)e * 320 + 2 * lane);
        ull fm0 = fp[0], fm1 = fp[32], fm2 = fp[64], fm3 = fp[96], fm4 = fp[128];

        #pragma unroll
        for (int f = 0; f < FULLC; ++f) {
            ulonglong2 wA = *(const ulonglong2*)(wp + f * 8);
            ulonglong2 wB = *(const ulonglong2*)(wp + f * 8 + 2);
            ull w4 = wp[f * 8 + 4];
            ull r = acc[f];
            fma2(r, wA.x, fm0);
            fma2(r, wA.y, fm1);
            fma2(r, wB.x, fm2);
            fma2(r, wB.y, fm3);
            fma2(r, w4,   fm4);
            acc[f] = r;
        }
        __syncwarp();
    }

    float* ob = out + (size_t)node * 1600 + 2 * lane;
    #pragma unroll
    for (int f = 0; f < FULLC; ++f) {
        float2 rv = unpk(acc[f]);
        *(float2*)(ob + f * 64) = rv;
    }
}

extern "C" void kernel_launch(void* const* d_in, const int* in_sizes, int n_in,
                              void* d_out, int out_size)
{
    const int*   species   = (const int*)  d_in[0];
    const float* dist      = (const float*)d_in[1];
    const int*   senders   = (const int*)  d_in[2];
    const int*   receivers = (const int*)  d_in[3];
    const float* wig       = (const float*)d_in[4];
    const float* env       = (const float*)d_in[5];
    const float* semb      = (const float*)d_in[6];
    const float* remb      = (const float*)d_in[7];
    const float* W1  = (const float*)d_in[8];
    const float* b1  = (const float*)d_in[9];
    const float* g1  = (const float*)d_in[10];
    const float* be1 = (const float*)d_in[11];
    const float* W2  = (const float*)d_in[12];
    const float* b2  = (const float*)d_in[13];
    const float* g2  = (const float*)d_in[14];
    const float* be2 = (const float*)d_in[15];
    const float* W3  = (const float*)d_in[16];
    const float* b3  = (const float*)d_in[17];
    float* out = (float*)d_out;

    cudaFuncSetAttribute(mlp_kernel,
                         cudaFuncAttributeMaxDynamicSharedMemorySize, SM1_BYTES);

    species_kernel<<<NSPEC, 64>>>(semb, remb, W1, b1);
    zero_kernel<<<(NNODES + 1023) / 1024, 1024>>>();
    hist_kernel<<<(E_TOTAL + 255) / 256, 256>>>(receivers);
    scan_kernel<<<1, 1024>>>();
    fill_kernel<<<(E_TOTAL + 255) / 256, 256>>>(receivers);
    mlp_kernel<<<(E_TOTAL + T1 - 1) / T1, 256, SM1_BYTES>>>(
        species, dist, senders, receivers,
        W1, g1, be1, W2, b2, g2, be2, W3, b3);
    wigner_gather<<<(NNODES + 7) / 8, 256>>>(wig, env, out);
}

// round 10
// speedup vs baseline: 1.1260x; 1.0444x over previous
#include <cuda_runtime.h>
#include <math.h>

#define E_TOTAL 400000
#define NNODES  12500
#define T1      256     // edges per CTA, kernel 1
#define PH      66      // smem row pitch (floats)
#define FULLC   25
#define MALL    19
#define NSPEC   90

typedef unsigned long long ull;

// scratch (static device globals; no allocation in kernel_launch)
__device__ float F_buf[(size_t)E_TOTAL * 320];
__device__ int   d_cnt[NNODES];
__device__ int   d_cur[NNODES];
__device__ int   d_offs[NNODES + 1];
__device__ int   d_eids[E_TOTAL];
__device__ float SPb[NSPEC * 64];                // semb @ W1[128:192] + b1
__device__ float RPb[NSPEC * 64];                // remb @ W1[192:256]

__device__ __forceinline__ ull pack2(float x) {
    ull r; asm("mov.b64 %0,{%1,%1};" : "=l"(r) : "f"(x)); return r;
}
__device__ __forceinline__ ull pack2xy(float x, float y) {
    ull r; asm("mov.b64 %0,{%1,%2};" : "=l"(r) : "f"(x), "f"(y)); return r;
}
__device__ __forceinline__ void fma2(ull& d, ull a, ull b) {
    asm("fma.rn.f32x2 %0,%1,%2,%0;" : "+l"(d) : "l"(a), "l"(b));
}
__device__ __forceinline__ float2 unpk(ull v) {
    float2 o; asm("mov.b64 {%0,%1},%2;" : "=f"(o.x), "=f"(o.y) : "l"(v)); return o;
}

// permuted float4 slot within a 64-float W row (conflict-free b-loads)
__device__ __forceinline__ int wperm(int c4) { return ((c4 & 1) << 3) | (c4 >> 1); }

// ---------------------------------------------------------------- CSR build
__global__ void zero_kernel() {
    int i = blockIdx.x * blockDim.x + threadIdx.x;
    if (i < NNODES) { d_cnt[i] = 0; d_cur[i] = 0; }
}
__global__ void hist_kernel(const int* __restrict__ receivers) {
    int e = blockIdx.x * blockDim.x + threadIdx.x;
    if (e < E_TOTAL) atomicAdd(&d_cnt[receivers[e]], 1);
}
__global__ void scan_kernel() {
    __shared__ int s[1024];
    const int CH = (NNODES + 1023) / 1024;   // 13
    int t = threadIdx.x;
    int base = t * CH;
    int loc[CH];
    int sum = 0;
    #pragma unroll
    for (int i = 0; i < CH; ++i) {
        int v = (base + i < NNODES) ? d_cnt[base + i] : 0;
        loc[i] = sum; sum += v;
    }
    s[t] = sum;
    __syncthreads();
    for (int off = 1; off < 1024; off <<= 1) {
        int v = s[t];
        int u = (t >= off) ? s[t - off] : 0;
        __syncthreads();
        s[t] = v + u;
        __syncthreads();
    }
    int excl = (t > 0) ? s[t - 1] : 0;
    #pragma unroll
    for (int i = 0; i < CH; ++i)
        if (base + i < NNODES) d_offs[base + i] = excl + loc[i];
    if (t == 1023) d_offs[NNODES] = s[1023];
}
__global__ void fill_kernel(const int* __restrict__ receivers) {
    int e = blockIdx.x * blockDim.x + threadIdx.x;
    if (e < E_TOTAL) {
        int r = receivers[e];
        int pos = atomicAdd(&d_cur[r], 1);
        d_eids[d_offs[r] + pos] = e;
    }
}

// -------------------------------------------- species projection precompute
__global__ void species_kernel(const float* __restrict__ semb,
                               const float* __restrict__ remb,
                               const float* __restrict__ W1,
                               const float* __restrict__ b1)
{
    int s = blockIdx.x;
    int c = threadIdx.x;
    float sp = b1[c], rp = 0.0f;
    #pragma unroll 8
    for (int k = 0; k < 64; ++k) {
        sp += semb[s * 64 + k] * W1[(128 + k) * 64 + c];
        rp += remb[s * 64 + k] * W1[(192 + k) * 64 + c];
    }
    SPb[s * 64 + c] = sp;
    RPb[s * 64 + c] = rp;
}

// ---------------------------------------------------------------- MLP GEMM
// 8 rows x 8 cols per thread; 256 threads cover 256 rows x 64 cols.
__device__ __forceinline__ void gemm64(const float* __restrict__ As,
                                       const ull*  __restrict__ Wp,
                                       int row0, int cj, ull acc[32])
{
    #pragma unroll 4
    for (int k2 = 0; k2 < 32; ++k2) {
        float2 a8[8];
        #pragma unroll
        for (int r = 0; r < 8; ++r)
            a8[r] = *(const float2*)(As + (row0 + r) * PH + 2 * k2);
        #pragma unroll
        for (int kk = 0; kk < 2; ++kk) {
            int k = 2 * k2 + kk;
            ulonglong2 bA = *(const ulonglong2*)(Wp + k * 32 + cj * 2);
            ulonglong2 bB = *(const ulonglong2*)(Wp + k * 32 + 16 + cj * 2);
            #pragma unroll
            for (int r = 0; r < 8; ++r) {
                ull p = pack2(kk ? a8[r].y : a8[r].x);
                fma2(acc[r * 4 + 0], p, bA.x);
                fma2(acc[r * 4 + 1], p, bA.y);
                fma2(acc[r * 4 + 2], p, bB.x);
                fma2(acc[r * 4 + 3], p, bB.y);
            }
        }
    }
}

// In-register LayerNorm + SiLU over 8 rows x 8 cols (row spread across 8 lanes,
// cj = lane&7, shuffle masks 1/2/4), then float2-store rows to smem tile
// (PH=66 -> odd rows are only 8B aligned; float4 stores would fault).
__device__ __forceinline__ void ln_silu_reg_store(ull acc[32], float* __restrict__ H,
                                                  int row0, int cj,
                                                  const float* __restrict__ g,
                                                  const float* __restrict__ be,
                                                  const float* __restrict__ bias)
{
    float4 gl = ((const float4*)g)[cj * 2];
    float4 gh = ((const float4*)g)[cj * 2 + 1];
    float4 el = ((const float4*)be)[cj * 2];
    float4 eh = ((const float4*)be)[cj * 2 + 1];
    float4 bl = make_float4(0, 0, 0, 0), bh = bl;
    if (bias) {
        bl = ((const float4*)bias)[cj * 2];
        bh = ((const float4*)bias)[cj * 2 + 1];
    }
    float gv[8] = {gl.x, gl.y, gl.z, gl.w, gh.x, gh.y, gh.z, gh.w};
    float ev[8] = {el.x, el.y, el.z, el.w, eh.x, eh.y, eh.z, eh.w};
    #pragma unroll
    for (int r = 0; r < 8; ++r) {
        float2 e0 = unpk(acc[4*r+0]); float2 e1 = unpk(acc[4*r+1]);
        float2 e2 = unpk(acc[4*r+2]); float2 e3 = unpk(acc[4*r+3]);
        float v[8] = { e0.x + bl.x, e0.y + bl.y, e1.x + bl.z, e1.y + bl.w,
                       e2.x + bh.x, e2.y + bh.y, e3.x + bh.z, e3.y + bh.w };
        float s = 0.0f, s2 = 0.0f;
        #pragma unroll
        for (int j = 0; j < 8; ++j) { s += v[j]; s2 += v[j] * v[j]; }
        #pragma unroll
        for (int o = 4; o > 0; o >>= 1) {
            s  += __shfl_xor_sync(0xffffffffu, s,  o);
            s2 += __shfl_xor_sync(0xffffffffu, s2, o);
        }
        float mu  = s * (1.0f / 64.0f);
        float var = s2 * (1.0f / 64.0f) - mu * mu;
        float rs  = rsqrtf(fmaxf(var, 0.0f) + 1e-5f);
        #pragma unroll
        for (int j = 0; j < 8; ++j) {
            float x = (v[j] - mu) * rs * gv[j] + ev[j];
            v[j] = x / (1.0f + __expf(-x));
        }
        float* p = H + (row0 + r) * PH + cj * 8;
        *(float2*)(p)     = make_float2(v[0], v[1]);
        *(float2*)(p + 2) = make_float2(v[2], v[3]);
        *(float2*)(p + 4) = make_float2(v[4], v[5]);
        *(float2*)(p + 6) = make_float2(v[6], v[7]);
    }
}

// load one 64x64 W chunk into a permuted smem slot (256 threads)
__device__ __forceinline__ void ldW(float* __restrict__ Wslot,
                                    const float* __restrict__ Wsrc, int tid,
                                    int src_row_pitch_f4)
{
    #pragma unroll
    for (int q = 0; q < 4; ++q) {
        int lin = tid + 256 * q;
        int k = lin >> 4, c4 = lin & 15;
        ((float4*)Wslot)[k * 16 + wperm(c4)] =
            ((const float4*)Wsrc)[k * src_row_pitch_f4 + c4];
    }
}

// smem: tile buffer + 2 W slots + species idx
#define SM1_FLOATS (T1 * PH + 2 * 64 * 64 + 64)
#define SM1_BYTES  (SM1_FLOATS * 4 + 2048 + 1024)

__global__ __launch_bounds__(256, 2)
void mlp_kernel(const int*   __restrict__ species,
                const float* __restrict__ dist,
                const int*   __restrict__ senders,
                const int*   __restrict__ receivers,
                const float* __restrict__ W1,
                const float* __restrict__ g1, const float* __restrict__ be1,
                const float* __restrict__ W2, const float* __restrict__ b2,
                const float* __restrict__ g2, const float* __restrict__ be2,
                const float* __restrict__ W3, const float* __restrict__ b3)
{
    extern __shared__ float sm[];
    float* Xc  = sm;                        // X chunk -> H1 -> H2
    float* Ws0 = Xc + T1 * PH;
    float* Ws1 = Ws0 + 64 * 64;
    int*   spS = (int*)(Ws1 + 64 * 64 + 64);
    int*   spR = spS + T1;

    const int tid  = threadIdx.x;           // 0..255
    const int cj   = tid & 7;
    const int ri   = tid >> 3;
    const int row0 = 8 * ri;
    const int base = blockIdx.x * T1;

    {
        int eg = base + tid;
        if (eg >= E_TOTAL) eg = E_TOTAL - 1;
        spS[tid] = species[senders[eg]];
        spR[tid] = species[receivers[eg]];
    }

    // preload both W1 chunks + X chunk 0
    ldW(Ws0, W1, tid, 16);
    ldW(Ws1, W1 + 64 * 64, tid, 16);
    #pragma unroll
    for (int q = 0; q < 32; ++q) {
        int lin = tid + 256 * q;
        int row = lin >> 5, c2 = lin & 31;
        int eg = base + row;
        if (eg >= E_TOTAL) eg = E_TOTAL - 1;
        float2 v = ((const float2*)dist)[(size_t)eg * 64 + c2];
        *(float2*)(Xc + row * PH + c2 * 2) = v;
    }
    __syncthreads();

    // ---- stage 1 acc init from precomputed species projections (incl. b1)
    ull acc[32];
    #pragma unroll
    for (int r = 0; r < 8; ++r) {
        int row = row0 + r;
        int ss = spS[row], sr = spR[row];
        float4 u0 = ((const float4*)SPb)[ss * 16 + cj * 2];
        float4 u1 = ((const float4*)SPb)[ss * 16 + cj * 2 + 1];
        float4 v0 = ((const float4*)RPb)[sr * 16 + cj * 2];
        float4 v1 = ((const float4*)RPb)[sr * 16 + cj * 2 + 1];
        acc[4*r+0] = pack2xy(u0.x + v0.x, u0.y + v0.y);
        acc[4*r+1] = pack2xy(u0.z + v0.z, u0.w + v0.w);
        acc[4*r+2] = pack2xy(u1.x + v1.x, u1.y + v1.y);
        acc[4*r+3] = pack2xy(u1.z + v1.z, u1.w + v1.w);
    }

    // ---- stage 1: += dist @ W1 (chunk 0 then chunk 1)
    gemm64(Xc, (const ull*)Ws0, row0, cj, acc);
    __syncthreads();
    #pragma unroll
    for (int q = 0; q < 32; ++q) {
        int lin = tid + 256 * q;
        int row = lin >> 5, c2 = lin & 31;
        int eg = base + row;
        if (eg >= E_TOTAL) eg = E_TOTAL - 1;
        float2 v = ((const float2*)dist)[(size_t)eg * 64 + 32 + c2];
        *(float2*)(Xc + row * PH + c2 * 2) = v;
    }
    __syncthreads();
    gemm64(Xc, (const ull*)Ws1, row0, cj, acc);
    __syncthreads();            // all gemms done before H1 overwrites Xc

    // ---- E1: in-reg LN+SiLU -> H1 in Xc; prefetch W2 into Ws0
    ln_silu_reg_store(acc, Xc, row0, cj, g1, be1, nullptr);
    ldW(Ws0, W2, tid, 16);
    __syncthreads();

    // ---- stage 2: H2 = H1 @ W2
    #pragma unroll
    for (int i = 0; i < 32; ++i) acc[i] = 0ull;
    gemm64(Xc, (const ull*)Ws0, row0, cj, acc);
    __syncthreads();            // all reads of H1 done before H2 overwrites

    // ---- E2: +b2, LN+SiLU -> H2 in Xc; prefetch W3 m=0 into Ws1
    ln_silu_reg_store(acc, Xc, row0, cj, g2, be2, b2);
    ldW(Ws1, W3, tid, 80);
    __syncthreads();

    // ---- stage 3: F_m = H2 @ W3[:, 64m:64m+64] + b3 -> F_buf (double-buffered W)
    for (int m = 0; m < 5; ++m) {
        const float* Wcur = (m & 1) ? Ws0 : Ws1;
        #pragma unroll
        for (int i = 0; i < 32; ++i) acc[i] = 0ull;
        gemm64(Xc, (const ull*)Wcur, row0, cj, acc);

        float4 bl = ((const float4*)b3)[m * 16 + cj * 2];
        float4 bh = ((const float4*)b3)[m * 16 + cj * 2 + 1];
        #pragma unroll
        for (int r = 0; r < 8; ++r) {
            int eg = base + row0 + r;
            if (eg >= E_TOTAL) continue;
            float2 e0 = unpk(acc[4*r+0]); float2 e1 = unpk(acc[4*r+1]);
            float2 e2 = unpk(acc[4*r+2]); float2 e3 = unpk(acc[4*r+3]);
            float* p = F_buf + (size_t)eg * 320 + m * 64 + cj * 8;
            *(float4*)(p)     = make_float4(e0.x + bl.x, e0.y + bl.y, e1.x + bl.z, e1.y + bl.w);
            *(float4*)(p + 4) = make_float4(e2.x + bh.x, e2.y + bh.y, e3.x + bh.z, e3.y + bh.w);
        }
        if (m < 4) {
            // next chunk starts at column (m+1)*64 -> offset (m+1)*64 FLOATS
            ldW((m & 1) ? Ws1 : Ws0, W3 + (m + 1) * 64, tid, 80);
            __syncthreads();
        }
    }
}

// --------------------------------- kernel 2: gather per node, no atomics
__global__ __launch_bounds__(256)
void wigner_gather(const float* __restrict__ wig,
                   const float* __restrict__ env,
                   float* __restrict__ out)
{
    __shared__ ull wbp[8][25 * 8];
    const int tid  = threadIdx.x;
    const int lane = tid & 31;
    const int warp = tid >> 5;
    const int node = blockIdx.x * 8 + warp;
    if (node >= NNODES) return;

    ull acc[FULLC];
    #pragma unroll
    for (int f = 0; f < FULLC; ++f) acc[f] = 0ull;

    const int beg = d_offs[node];
    const int end = d_offs[node + 1];
    ull* wp = wbp[warp];

    for (int idx = beg; idx < end; ++idx) {
        int e = d_eids[idx];
        float sc = env[e] * 0.2f;
        const float* wr = wig + (size_t)e * (FULLC * MALL);
        #pragma unroll
        for (int t = 0; t < 4; ++t) {
            int lin = lane + 32 * t;
            if (lin < 125) {
                int f = lin / 5;
                int m = lin - 5 * f;
                wp[f * 8 + m] = pack2(wr[f * MALL + m] * sc);
            }
        }
        __syncwarp();

        const ull* fp = (const ull*)(F_buf + (size_t)e * 320 + 2 * lane);
        ull fm0 = fp[0], fm1 = fp[32], fm2 = fp[64], fm3 = fp[96], fm4 = fp[128];

        #pragma unroll
        for (int f = 0; f < FULLC; ++f) {
            ulonglong2 wA = *(const ulonglong2*)(wp + f * 8);
            ulonglong2 wB = *(const ulonglong2*)(wp + f * 8 + 2);
            ull w4 = wp[f * 8 + 4];
            ull r = acc[f];
            fma2(r, wA.x, fm0);
            fma2(r, wA.y, fm1);
            fma2(r, wB.x, fm2);
            fma2(r, wB.y, fm3);
            fma2(r, w4,   fm4);
            acc[f] = r;
        }
        __syncwarp();
    }

    float* ob = out + (size_t)node * 1600 + 2 * lane;
    #pragma unroll
    for (int f = 0; f < FULLC; ++f) {
        float2 rv = unpk(acc[f]);
        *(float2*)(ob + f * 64) = rv;
    }
}

extern "C" void kernel_launch(void* const* d_in, const int* in_sizes, int n_in,
                              void* d_out, int out_size)
{
    const int*   species   = (const int*)  d_in[0];
    const float* dist      = (const float*)d_in[1];
    const int*   senders   = (const int*)  d_in[2];
    const int*   receivers = (const int*)  d_in[3];
    const float* wig       = (const float*)d_in[4];
    const float* env       = (const float*)d_in[5];
    const float* semb      = (const float*)d_in[6];
    const float* remb      = (const float*)d_in[7];
    const float* W1  = (const float*)d_in[8];
    const float* b1  = (const float*)d_in[9];
    const float* g1  = (const float*)d_in[10];
    const float* be1 = (const float*)d_in[11];
    const float* W2  = (const float*)d_in[12];
    const float* b2  = (const float*)d_in[13];
    const float* g2  = (const float*)d_in[14];
    const float* be2 = (const float*)d_in[15];
    const float* W3  = (const float*)d_in[16];
    const float* b3  = (const float*)d_in[17];
    float* out = (float*)d_out;

    cudaFuncSetAttribute(mlp_kernel,
                         cudaFuncAttributeMaxDynamicSharedMemorySize, SM1_BYTES);

    species_kernel<<<NSPEC, 64>>>(semb, remb, W1, b1);
    zero_kernel<<<(NNODES + 1023) / 1024, 1024>>>();
    hist_kernel<<<(E_TOTAL + 255) / 256, 256>>>(receivers);
    scan_kernel<<<1, 1024>>>();
    fill_kernel<<<(E_TOTAL + 255) / 256, 256>>>(receivers);
    mlp_kernel<<<(E_TOTAL + T1 - 1) / T1, 256, SM1_BYTES>>>(
        species, dist, senders, receivers,
        W1, g1, be1, W2, b2, g2, be2, W3, b3);
    wigner_gather<<<(NNODES + 7) / 8, 256>>>(wig, env, out);
}

// round 11
// speedup vs baseline: 1.2779x; 1.1349x over previous
#include <cuda_runtime.h>
#include <math.h>

#define E_TOTAL 400000
#define NNODES  12500
#define T1      256     // edges per CTA, kernel 1
#define PH      66      // smem row pitch (floats)
#define FULLC   25
#define MALL    19
#define NSPEC   90

typedef unsigned long long ull;

// scratch (static device globals; no allocation in kernel_launch)
__device__ float F_buf[(size_t)E_TOTAL * 320];
__device__ int   d_cnt[NNODES];      // zero-initialized; re-zeroed by wigner_gather
__device__ int   d_cur[NNODES];      // zero-initialized; re-zeroed by wigner_gather
__device__ int   d_offs[NNODES + 1];
__device__ int   d_eids[E_TOTAL];
__device__ float SPb[NSPEC * 64];    // semb @ W1[128:192] + b1
__device__ float RPb[NSPEC * 64];    // remb @ W1[192:256]

__device__ __forceinline__ ull pack2(float x) {
    ull r; asm("mov.b64 %0,{%1,%1};" : "=l"(r) : "f"(x)); return r;
}
__device__ __forceinline__ ull pack2xy(float x, float y) {
    ull r; asm("mov.b64 %0,{%1,%2};" : "=l"(r) : "f"(x), "f"(y)); return r;
}
__device__ __forceinline__ void fma2(ull& d, ull a, ull b) {
    asm("fma.rn.f32x2 %0,%1,%2,%0;" : "+l"(d) : "l"(a), "l"(b));
}
__device__ __forceinline__ float2 unpk(ull v) {
    float2 o; asm("mov.b64 {%0,%1},%2;" : "=f"(o.x), "=f"(o.y) : "l"(v)); return o;
}

// permuted float4 slot within a 64-float W row (conflict-free b-loads)
__device__ __forceinline__ int wperm(int c4) { return ((c4 & 1) << 3) | (c4 >> 1); }

// ---------------------------------------------------------------- CSR build
__global__ void hist_kernel(const int* __restrict__ receivers) {
    int e = blockIdx.x * blockDim.x + threadIdx.x;
    if (e < E_TOTAL) atomicAdd(&d_cnt[receivers[e]], 1);
}
__global__ void scan_kernel() {
    __shared__ int s[1024];
    const int CH = (NNODES + 1023) / 1024;   // 13
    int t = threadIdx.x;
    int base = t * CH;
    int loc[CH];
    int sum = 0;
    #pragma unroll
    for (int i = 0; i < CH; ++i) {
        int v = (base + i < NNODES) ? d_cnt[base + i] : 0;
        loc[i] = sum; sum += v;
    }
    s[t] = sum;
    __syncthreads();
    for (int off = 1; off < 1024; off <<= 1) {
        int v = s[t];
        int u = (t >= off) ? s[t - off] : 0;
        __syncthreads();
        s[t] = v + u;
        __syncthreads();
    }
    int excl = (t > 0) ? s[t - 1] : 0;
    #pragma unroll
    for (int i = 0; i < CH; ++i)
        if (base + i < NNODES) d_offs[base + i] = excl + loc[i];
    if (t == 1023) d_offs[NNODES] = s[1023];
}
__global__ void fill_kernel(const int* __restrict__ receivers) {
    int e = blockIdx.x * blockDim.x + threadIdx.x;
    if (e < E_TOTAL) {
        int r = receivers[e];
        int pos = atomicAdd(&d_cur[r], 1);
        d_eids[d_offs[r] + pos] = e;
    }
}

// -------------------------------------------- species projection precompute
__global__ void species_kernel(const float* __restrict__ semb,
                               const float* __restrict__ remb,
                               const float* __restrict__ W1,
                               const float* __restrict__ b1)
{
    int s = blockIdx.x;
    int c = threadIdx.x;
    float sp = b1[c], rp = 0.0f;
    #pragma unroll 8
    for (int k = 0; k < 64; ++k) {
        sp += semb[s * 64 + k] * W1[(128 + k) * 64 + c];
        rp += remb[s * 64 + k] * W1[(192 + k) * 64 + c];
    }
    SPb[s * 64 + c] = sp;
    RPb[s * 64 + c] = rp;
}

// ---------------------------------------------------------------- MLP GEMM
// 8 rows x 8 cols per thread; 256 threads cover 256 rows x 64 cols.
__device__ __forceinline__ void gemm64(const float* __restrict__ As,
                                       const ull*  __restrict__ Wp,
                                       int row0, int cj, ull acc[32])
{
    #pragma unroll 4
    for (int k2 = 0; k2 < 32; ++k2) {
        float2 a8[8];
        #pragma unroll
        for (int r = 0; r < 8; ++r)
            a8[r] = *(const float2*)(As + (row0 + r) * PH + 2 * k2);
        #pragma unroll
        for (int kk = 0; kk < 2; ++kk) {
            int k = 2 * k2 + kk;
            ulonglong2 bA = *(const ulonglong2*)(Wp + k * 32 + cj * 2);
            ulonglong2 bB = *(const ulonglong2*)(Wp + k * 32 + 16 + cj * 2);
            #pragma unroll
            for (int r = 0; r < 8; ++r) {
                ull p = pack2(kk ? a8[r].y : a8[r].x);
                fma2(acc[r * 4 + 0], p, bA.x);
                fma2(acc[r * 4 + 1], p, bA.y);
                fma2(acc[r * 4 + 2], p, bB.x);
                fma2(acc[r * 4 + 3], p, bB.y);
            }
        }
    }
}

// In-register LayerNorm + SiLU over 8 rows x 8 cols (row spread across 8 lanes,
// cj = lane&7, shuffle masks 1/2/4), then float2-store rows to smem tile
// (PH=66 -> odd rows are only 8B aligned; float4 stores would fault).
__device__ __forceinline__ void ln_silu_reg_store(ull acc[32], float* __restrict__ H,
                                                  int row0, int cj,
                                                  const float* __restrict__ g,
                                                  const float* __restrict__ be,
                                                  const float* __restrict__ bias)
{
    float4 gl = ((const float4*)g)[cj * 2];
    float4 gh = ((const float4*)g)[cj * 2 + 1];
    float4 el = ((const float4*)be)[cj * 2];
    float4 eh = ((const float4*)be)[cj * 2 + 1];
    float4 bl = make_float4(0, 0, 0, 0), bh = bl;
    if (bias) {
        bl = ((const float4*)bias)[cj * 2];
        bh = ((const float4*)bias)[cj * 2 + 1];
    }
    float gv[8] = {gl.x, gl.y, gl.z, gl.w, gh.x, gh.y, gh.z, gh.w};
    float ev[8] = {el.x, el.y, el.z, el.w, eh.x, eh.y, eh.z, eh.w};
    #pragma unroll
    for (int r = 0; r < 8; ++r) {
        float2 e0 = unpk(acc[4*r+0]); float2 e1 = unpk(acc[4*r+1]);
        float2 e2 = unpk(acc[4*r+2]); float2 e3 = unpk(acc[4*r+3]);
        float v[8] = { e0.x + bl.x, e0.y + bl.y, e1.x + bl.z, e1.y + bl.w,
                       e2.x + bh.x, e2.y + bh.y, e3.x + bh.z, e3.y + bh.w };
        float s = 0.0f, s2 = 0.0f;
        #pragma unroll
        for (int j = 0; j < 8; ++j) { s += v[j]; s2 += v[j] * v[j]; }
        #pragma unroll
        for (int o = 4; o > 0; o >>= 1) {
            s  += __shfl_xor_sync(0xffffffffu, s,  o);
            s2 += __shfl_xor_sync(0xffffffffu, s2, o);
        }
        float mu  = s * (1.0f / 64.0f);
        float var = s2 * (1.0f / 64.0f) - mu * mu;
        float rs  = rsqrtf(fmaxf(var, 0.0f) + 1e-5f);
        #pragma unroll
        for (int j = 0; j < 8; ++j) {
            float x = (v[j] - mu) * rs * gv[j] + ev[j];
            v[j] = x / (1.0f + __expf(-x));
        }
        float* p = H + (row0 + r) * PH + cj * 8;
        *(float2*)(p)     = make_float2(v[0], v[1]);
        *(float2*)(p + 2) = make_float2(v[2], v[3]);
        *(float2*)(p + 4) = make_float2(v[4], v[5]);
        *(float2*)(p + 6) = make_float2(v[6], v[7]);
    }
}

// load one 64x64 W chunk into a permuted smem slot (256 threads)
__device__ __forceinline__ void ldW(float* __restrict__ Wslot,
                                    const float* __restrict__ Wsrc, int tid,
                                    int src_row_pitch_f4)
{
    #pragma unroll
    for (int q = 0; q < 4; ++q) {
        int lin = tid + 256 * q;
        int k = lin >> 4, c4 = lin & 15;
        ((float4*)Wslot)[k * 16 + wperm(c4)] =
            ((const float4*)Wsrc)[k * src_row_pitch_f4 + c4];
    }
}

// smem: tile buffer + 2 W slots + species idx
#define SM1_FLOATS (T1 * PH + 2 * 64 * 64 + 64)
#define SM1_BYTES  (SM1_FLOATS * 4 + 2048 + 1024)

__global__ __launch_bounds__(256, 2)
void mlp_kernel(const int*   __restrict__ species,
                const float* __restrict__ dist,
                const int*   __restrict__ senders,
                const int*   __restrict__ receivers,
                const float* __restrict__ W1,
                const float* __restrict__ g1, const float* __restrict__ be1,
                const float* __restrict__ W2, const float* __restrict__ b2,
                const float* __restrict__ g2, const float* __restrict__ be2,
                const float* __restrict__ W3, const float* __restrict__ b3)
{
    extern __shared__ float sm[];
    float* Xc  = sm;                        // X chunk -> H1 -> H2
    float* Ws0 = Xc + T1 * PH;
    float* Ws1 = Ws0 + 64 * 64;
    int*   spS = (int*)(Ws1 + 64 * 64 + 64);
    int*   spR = spS + T1;

    const int tid  = threadIdx.x;           // 0..255
    const int cj   = tid & 7;
    const int ri   = tid >> 3;
    const int row0 = 8 * ri;
    const int base = blockIdx.x * T1;

    {
        int eg = base + tid;
        if (eg >= E_TOTAL) eg = E_TOTAL - 1;
        spS[tid] = species[senders[eg]];
        spR[tid] = species[receivers[eg]];
    }

    // preload both W1 chunks + X chunk 0
    ldW(Ws0, W1, tid, 16);
    ldW(Ws1, W1 + 64 * 64, tid, 16);
    #pragma unroll
    for (int q = 0; q < 32; ++q) {
        int lin = tid + 256 * q;
        int row = lin >> 5, c2 = lin & 31;
        int eg = base + row;
        if (eg >= E_TOTAL) eg = E_TOTAL - 1;
        float2 v = ((const float2*)dist)[(size_t)eg * 64 + c2];
        *(float2*)(Xc + row * PH + c2 * 2) = v;
    }
    __syncthreads();

    // ---- stage 1 acc init from precomputed species projections (incl. b1)
    ull acc[32];
    #pragma unroll
    for (int r = 0; r < 8; ++r) {
        int row = row0 + r;
        int ss = spS[row], sr = spR[row];
        float4 u0 = ((const float4*)SPb)[ss * 16 + cj * 2];
        float4 u1 = ((const float4*)SPb)[ss * 16 + cj * 2 + 1];
        float4 v0 = ((const float4*)RPb)[sr * 16 + cj * 2];
        float4 v1 = ((const float4*)RPb)[sr * 16 + cj * 2 + 1];
        acc[4*r+0] = pack2xy(u0.x + v0.x, u0.y + v0.y);
        acc[4*r+1] = pack2xy(u0.z + v0.z, u0.w + v0.w);
        acc[4*r+2] = pack2xy(u1.x + v1.x, u1.y + v1.y);
        acc[4*r+3] = pack2xy(u1.z + v1.z, u1.w + v1.w);
    }

    // ---- stage 1: += dist @ W1 (chunk 0 then chunk 1)
    gemm64(Xc, (const ull*)Ws0, row0, cj, acc);
    __syncthreads();
    #pragma unroll
    for (int q = 0; q < 32; ++q) {
        int lin = tid + 256 * q;
        int row = lin >> 5, c2 = lin & 31;
        int eg = base + row;
        if (eg >= E_TOTAL) eg = E_TOTAL - 1;
        float2 v = ((const float2*)dist)[(size_t)eg * 64 + 32 + c2];
        *(float2*)(Xc + row * PH + c2 * 2) = v;
    }
    __syncthreads();
    gemm64(Xc, (const ull*)Ws1, row0, cj, acc);
    __syncthreads();            // all gemms done before H1 overwrites Xc

    // ---- E1: in-reg LN+SiLU -> H1 in Xc; prefetch W2 into Ws0
    ln_silu_reg_store(acc, Xc, row0, cj, g1, be1, nullptr);
    ldW(Ws0, W2, tid, 16);
    __syncthreads();

    // ---- stage 2: H2 = H1 @ W2
    #pragma unroll
    for (int i = 0; i < 32; ++i) acc[i] = 0ull;
    gemm64(Xc, (const ull*)Ws0, row0, cj, acc);
    __syncthreads();            // all reads of H1 done before H2 overwrites

    // ---- E2: +b2, LN+SiLU -> H2 in Xc; prefetch W3 m=0 into Ws1
    ln_silu_reg_store(acc, Xc, row0, cj, g2, be2, b2);
    ldW(Ws1, W3, tid, 80);
    __syncthreads();

    // ---- stage 3: F_m = H2 @ W3[:, 64m:64m+64] + b3 -> F_buf (double-buffered W)
    for (int m = 0; m < 5; ++m) {
        const float* Wcur = (m & 1) ? Ws0 : Ws1;
        #pragma unroll
        for (int i = 0; i < 32; ++i) acc[i] = 0ull;
        gemm64(Xc, (const ull*)Wcur, row0, cj, acc);

        float4 bl = ((const float4*)b3)[m * 16 + cj * 2];
        float4 bh = ((const float4*)b3)[m * 16 + cj * 2 + 1];
        #pragma unroll
        for (int r = 0; r < 8; ++r) {
            int eg = base + row0 + r;
            if (eg >= E_TOTAL) continue;
            float2 e0 = unpk(acc[4*r+0]); float2 e1 = unpk(acc[4*r+1]);
            float2 e2 = unpk(acc[4*r+2]); float2 e3 = unpk(acc[4*r+3]);
            float* p = F_buf + (size_t)eg * 320 + m * 64 + cj * 8;
            *(float4*)(p)     = make_float4(e0.x + bl.x, e0.y + bl.y, e1.x + bl.z, e1.y + bl.w);
            *(float4*)(p + 4) = make_float4(e2.x + bh.x, e2.y + bh.y, e3.x + bh.z, e3.y + bh.w);
        }
        if (m < 4) {
            // next chunk starts at column (m+1)*64 -> offset (m+1)*64 FLOATS
            ldW((m & 1) ? Ws1 : Ws0, W3 + (m + 1) * 64, tid, 80);
            __syncthreads();
        }
    }
}

// --------------------------------- kernel 2: gather per node, no atomics,
// with register prefetch of the NEXT edge's wig/F/env before computing current.
__global__ __launch_bounds__(256)
void wigner_gather(const float* __restrict__ wig,
                   const float* __restrict__ env,
                   float* __restrict__ out)
{
    __shared__ ull wbp[8][25 * 8];
    const int tid  = threadIdx.x;
    const int lane = tid & 31;
    const int warp = tid >> 5;
    const int node = blockIdx.x * 8 + warp;
    if (node >= NNODES) return;

    ull acc[FULLC];
    #pragma unroll
    for (int f = 0; f < FULLC; ++f) acc[f] = 0ull;

    const int beg = d_offs[node];
    const int end = d_offs[node + 1];
    ull* wp = wbp[warp];

    // per-lane staged raw values for one edge
    const int f0 = (lane +  0) / 5,  m0 = (lane +  0) - 5 * f0;
    const int f1 = (lane + 32) / 5,  m1 = (lane + 32) - 5 * f1;
    const int f2 = (lane + 64) / 5,  m2 = (lane + 64) - 5 * f2;
    const int f3 = (lane + 96) / 5,  m3 = (lane + 96) - 5 * f3;   // lane+96 < 125 only if lane < 29

    float wrv0 = 0, wrv1 = 0, wrv2 = 0, wrv3 = 0, scv = 0;
    ull fr[5] = {0, 0, 0, 0, 0};

    auto load_raw = [&](int e) {
        scv = env[e] * 0.2f;
        const float* wr = wig + (size_t)e * (FULLC * MALL);
        wrv0 = wr[f0 * MALL + m0];
        wrv1 = wr[f1 * MALL + m1];
        wrv2 = wr[f2 * MALL + m2];
        if (lane < 29) wrv3 = wr[f3 * MALL + m3];
        const ull* fp = (const ull*)(F_buf + (size_t)e * 320 + 2 * lane);
        fr[0] = fp[0]; fr[1] = fp[32]; fr[2] = fp[64]; fr[3] = fp[96]; fr[4] = fp[128];
    };

    if (beg < end) load_raw(d_eids[beg]);

    for (int idx = beg; idx < end; ++idx) {
        // stage current edge (from registers) into smem, scaled+packed
        wp[f0 * 8 + m0] = pack2(wrv0 * scv);
        wp[f1 * 8 + m1] = pack2(wrv1 * scv);
        wp[f2 * 8 + m2] = pack2(wrv2 * scv);
        if (lane < 29) wp[f3 * 8 + m3] = pack2(wrv3 * scv);
        ull fc0 = fr[0], fc1 = fr[1], fc2 = fr[2], fc3 = fr[3], fc4 = fr[4];
        __syncwarp();

        // prefetch next edge's raw data (LDGs overlap the compute below)
        if (idx + 1 < end) load_raw(d_eids[idx + 1]);

        #pragma unroll
        for (int f = 0; f < FULLC; ++f) {
            ulonglong2 wA = *(const ulonglong2*)(wp + f * 8);
            ulonglong2 wB = *(const ulonglong2*)(wp + f * 8 + 2);
            ull w4 = wp[f * 8 + 4];
            ull r = acc[f];
            fma2(r, wA.x, fc0);
            fma2(r, wA.y, fc1);
            fma2(r, wB.x, fc2);
            fma2(r, wB.y, fc3);
            fma2(r, w4,   fc4);
            acc[f] = r;
        }
        __syncwarp();
    }

    float* ob = out + (size_t)node * 1600 + 2 * lane;
    #pragma unroll
    for (int f = 0; f < FULLC; ++f) {
        float2 rv = unpk(acc[f]);
        *(float2*)(ob + f * 64) = rv;
    }

    // leave CSR counters zeroed for the next launch (replaces zero_kernel)
    if (lane == 0) { d_cnt[node] = 0; d_cur[node] = 0; }
}

extern "C" void kernel_launch(void* const* d_in, const int* in_sizes, int n_in,
                              void* d_out, int out_size)
{
    const int*   species   = (const int*)  d_in[0];
    const float* dist      = (const float*)d_in[1];
    const int*   senders   = (const int*)  d_in[2];
    const int*   receivers = (const int*)  d_in[3];
    const float* wig       = (const float*)d_in[4];
    const float* env       = (const float*)d_in[5];
    const float* semb      = (const float*)d_in[6];
    const float* remb      = (const float*)d_in[7];
    const float* W1  = (const float*)d_in[8];
    const float* b1  = (const float*)d_in[9];
    const float* g1  = (const float*)d_in[10];
    const float* be1 = (const float*)d_in[11];
    const float* W2  = (const float*)d_in[12];
    const float* b2  = (const float*)d_in[13];
    const float* g2  = (const float*)d_in[14];
    const float* be2 = (const float*)d_in[15];
    const float* W3  = (const float*)d_in[16];
    const float* b3  = (const float*)d_in[17];
    float* out = (float*)d_out;

    cudaFuncSetAttribute(mlp_kernel,
                         cudaFuncAttributeMaxDynamicSharedMemorySize, SM1_BYTES);

    species_kernel<<<NSPEC, 64>>>(semb, remb, W1, b1);
    hist_kernel<<<(E_TOTAL + 255) / 256, 256>>>(receivers);
    scan_kernel<<<1, 1024>>>();
    fill_kernel<<<(E_TOTAL + 255) / 256, 256>>>(receivers);
    mlp_kernel<<<(E_TOTAL + T1 - 1) / T1, 256, SM1_BYTES>>>(
        species, dist, senders, receivers,
        W1, g1, be1, W2, b2, g2, be2, W3, b3);
    wigner_gather<<<(NNODES + 7) / 8, 256>>>(wig, env, out);
}